// round 1
// baseline (speedup 1.0000x reference)
#include <cuda_runtime.h>
#include <cuda_bf16.h>
#include <math.h>

// ---------------- problem constants ----------------
#define NN      10000
#define EE      30000
#define INDIM   1024
#define H1      4
#define C1      512
#define D1      2048        // H1*C1
#define H2      8
#define C2      460
#define D2      3680        // H2*C2
#define E2      40000       // EE + NN (self loops appended)

// ---------------- device scratch (static, no allocs) ----------------
__device__ int   g_src[EE];
__device__ int   g_dst[EE];
__device__ int   g_is64;

__device__ float g_q   [(size_t)NN * D1];
__device__ float g_k   [(size_t)NN * D1];
__device__ float g_v   [(size_t)NN * D1];
__device__ float g_skip[(size_t)NN * D1];
__device__ float g_agg [(size_t)NN * D1];   // becomes h after elu

__device__ float g_alpha[EE * H1];          // alpha, then ex
__device__ float g_amax1[NN * H1];
__device__ float g_den1 [NN * H1];

__device__ float g_gl  [(size_t)NN * D2];
__device__ float g_gr  [(size_t)NN * D2];

__device__ float g_a2   [E2 * H2];          // a, then ex
__device__ float g_amax2[NN * H2];
__device__ float g_den2 [NN * H2];

__device__ float g_accum[(size_t)NN * D2];  // per-head output accumulation

// ---------------- helpers ----------------
__device__ __forceinline__ void atomicMaxFloat(float* addr, float val) {
    int* ai = (int*)addr;
    int old = *ai;
    while (__int_as_float(old) < val) {
        int assumed = old;
        old = atomicCAS(ai, assumed, __float_as_int(val));
        if (old == assumed) break;
    }
}

// ---------------- edge_index dtype detect + convert ----------------
__global__ void detect_kernel(const int* w) {
    // int64 layout: odd 32-bit words are high halves == 0 (values < 10000).
    // int32 layout: odd words are dst values; 2000 consecutive zeros impossible.
    int all0 = 1;
    for (int i = 1; i < 4001; i += 2) {
        if (w[i] != 0) { all0 = 0; break; }
    }
    g_is64 = all0;
}

__global__ void convert_kernel(const void* ei) {
    int e = blockIdx.x * blockDim.x + threadIdx.x;
    if (e >= EE) return;
    if (g_is64) {
        const long long* p = (const long long*)ei;
        g_src[e] = (int)p[2 * e];
        g_dst[e] = (int)p[2 * e + 1];
    } else {
        const int* p = (const int*)ei;
        g_src[e] = p[2 * e];
        g_dst[e] = p[2 * e + 1];
    }
}

__global__ void fill_neginf(float* p, int n) {
    int i = blockIdx.x * blockDim.x + threadIdx.x;
    if (i < n) p[i] = -INFINITY;
}

// ---------------- SGEMM: C = A(MxK) * B(KxN) + bias, row-major ----------------
// 128x128 block tile, BK=16, 256 threads, 8x8 per thread.
#define TM 128
#define TN 128
#define TK 16

__global__ __launch_bounds__(256)
void sgemm_bias(const float* __restrict__ A, const float* __restrict__ B,
                const float* __restrict__ bias, float* __restrict__ C,
                int M, int N, int K)
{
    __shared__ float As[TK][TM];
    __shared__ float Bs[TK][TN];

    const int tid = threadIdx.x;        // 0..255
    const int bm  = blockIdx.y * TM;
    const int bn  = blockIdx.x * TN;
    const int tx  = tid & 15;           // 0..15
    const int ty  = tid >> 4;           // 0..15

    float acc[8][8];
    #pragma unroll
    for (int i = 0; i < 8; i++)
        #pragma unroll
        for (int j = 0; j < 8; j++) acc[i][j] = 0.f;

    for (int k0 = 0; k0 < K; k0 += TK) {
        // load A tile (128x16) : 512 float4, 2 per thread, transpose into As[k][m]
        #pragma unroll
        for (int t = 0; t < 2; t++) {
            int f   = tid + t * 256;
            int row = f >> 2;
            int kc  = (f & 3) << 2;
            int gr  = bm + row;
            float4 va = make_float4(0.f, 0.f, 0.f, 0.f);
            if (gr < M) va = *(const float4*)(A + (size_t)gr * K + k0 + kc);
            As[kc + 0][row] = va.x;
            As[kc + 1][row] = va.y;
            As[kc + 2][row] = va.z;
            As[kc + 3][row] = va.w;
        }
        // load B tile (16x128): 512 float4, 2 per thread
        #pragma unroll
        for (int t = 0; t < 2; t++) {
            int f  = tid + t * 256;
            int kr = f >> 5;
            int nc = (f & 31) << 2;
            int gc = bn + nc;
            float4 vb = make_float4(0.f, 0.f, 0.f, 0.f);
            if (gc < N) vb = *(const float4*)(B + (size_t)(k0 + kr) * N + gc);
            *(float4*)&Bs[kr][nc] = vb;
        }
        __syncthreads();

        #pragma unroll
        for (int kk = 0; kk < TK; kk++) {
            float a[8], b[8];
            #pragma unroll
            for (int i = 0; i < 8; i++) a[i] = As[kk][ty * 8 + i];
            #pragma unroll
            for (int j = 0; j < 8; j++) b[j] = Bs[kk][tx * 8 + j];
            #pragma unroll
            for (int i = 0; i < 8; i++)
                #pragma unroll
                for (int j = 0; j < 8; j++)
                    acc[i][j] += a[i] * b[j];
        }
        __syncthreads();
    }

    // write back (N is a multiple of 4, bn/tx*8 multiples of 4 -> float4 safe)
    #pragma unroll
    for (int i = 0; i < 8; i++) {
        int gr = bm + ty * 8 + i;
        if (gr >= M) continue;
        #pragma unroll
        for (int j = 0; j < 8; j += 4) {
            int gc = bn + tx * 8 + j;
            if (gc < N) {
                float4 o;
                o.x = acc[i][j + 0] + bias[gc + 0];
                o.y = acc[i][j + 1] + bias[gc + 1];
                o.z = acc[i][j + 2] + bias[gc + 2];
                o.w = acc[i][j + 3] + bias[gc + 3];
                *(float4*)(C + (size_t)gr * N + gc) = o;
            }
        }
    }
}

// ---------------- layer 1: alpha = <q[dst], k[src]> / sqrt(C1) ----------------
__global__ void alpha1_kernel() {
    int gw   = (blockIdx.x * blockDim.x + threadIdx.x) >> 5;
    int lane = threadIdx.x & 31;
    if (gw >= EE * H1) return;
    int e = gw >> 2, h = gw & 3;
    int s = g_src[e], d = g_dst[e];
    const float4* qp = (const float4*)(g_q + (size_t)d * D1 + h * C1);
    const float4* kp = (const float4*)(g_k + (size_t)s * D1 + h * C1);
    float sum = 0.f;
    #pragma unroll
    for (int c = lane; c < C1 / 4; c += 32) {
        float4 a = qp[c], b = kp[c];
        sum += a.x * b.x + a.y * b.y + a.z * b.z + a.w * b.w;
    }
    #pragma unroll
    for (int o = 16; o; o >>= 1) sum += __shfl_xor_sync(0xFFFFFFFFu, sum, o);
    if (lane == 0) {
        float val = sum * 0.04419417382415922f;  // 1/sqrt(512)
        g_alpha[e * H1 + h] = val;
        atomicMaxFloat(&g_amax1[d * H1 + h], val);
    }
}

__global__ void exp1_kernel() {
    int i = blockIdx.x * blockDim.x + threadIdx.x;
    if (i >= EE * H1) return;
    int e = i >> 2, h = i & 3;
    int d = g_dst[e];
    float ex = expf(g_alpha[i] - g_amax1[d * H1 + h]);
    g_alpha[i] = ex;
    atomicAdd(&g_den1[d * H1 + h], ex);
}

__global__ void agg1_kernel() {
    __shared__ float w[H1];
    int e = blockIdx.x;
    int s = g_src[e], d = g_dst[e];
    if (threadIdx.x < H1)
        w[threadIdx.x] = g_alpha[e * H1 + threadIdx.x] /
                         (g_den1[d * H1 + threadIdx.x] + 1e-16f);
    __syncthreads();
    const float* vp = g_v   + (size_t)s * D1;
    float*       ap = g_agg + (size_t)d * D1;
    for (int idx = threadIdx.x; idx < D1; idx += blockDim.x)
        atomicAdd(&ap[idx], vp[idx] * w[idx >> 9]);
}

// h = elu(agg + skip), in place into g_agg
__global__ void elu_kernel() {
    int i = blockIdx.x * blockDim.x + threadIdx.x;
    if (i >= NN * D1) return;
    float x = g_agg[i] + g_skip[i];
    g_agg[i] = x > 0.f ? x : expm1f(x);
}

// ---------------- layer 2 ----------------
__global__ void alpha2_kernel(const float* __restrict__ att) {
    int gw   = (blockIdx.x * blockDim.x + threadIdx.x) >> 5;
    int lane = threadIdx.x & 31;
    if (gw >= E2 * H2) return;
    int ee = gw >> 3, h = gw & 7;
    int s = ee < EE ? g_src[ee] : ee - EE;
    int d = ee < EE ? g_dst[ee] : ee - EE;
    const float* lp = g_gl + (size_t)s * D2 + h * C2;
    const float* rp = g_gr + (size_t)d * D2 + h * C2;
    const float* ap = att + h * C2;
    float sum = 0.f;
    for (int c = lane; c < C2; c += 32) {
        float eo = lp[c] + rp[c];
        eo = eo > 0.f ? eo : 0.2f * eo;
        sum += eo * ap[c];
    }
    #pragma unroll
    for (int o = 16; o; o >>= 1) sum += __shfl_xor_sync(0xFFFFFFFFu, sum, o);
    if (lane == 0) {
        g_a2[ee * H2 + h] = sum;
        atomicMaxFloat(&g_amax2[d * H2 + h], sum);
    }
}

__global__ void exp2_kernel() {
    int i = blockIdx.x * blockDim.x + threadIdx.x;
    if (i >= E2 * H2) return;
    int ee = i >> 3, h = i & 7;
    int d = ee < EE ? g_dst[ee] : ee - EE;
    float ex = expf(g_a2[i] - g_amax2[d * H2 + h]);
    g_a2[i] = ex;
    atomicAdd(&g_den2[d * H2 + h], ex);
}

__global__ void scatter2_kernel() {
    __shared__ float w[H2];
    int ee = blockIdx.x;
    int s = ee < EE ? g_src[ee] : ee - EE;
    int d = ee < EE ? g_dst[ee] : ee - EE;
    if (threadIdx.x < H2)
        w[threadIdx.x] = g_a2[ee * H2 + threadIdx.x] /
                         (g_den2[d * H2 + threadIdx.x] + 1e-16f);
    __syncthreads();
    const float* lp = g_gl    + (size_t)s * D2;
    float*       ap = g_accum + (size_t)d * D2;
    for (int idx = threadIdx.x; idx < D2; idx += blockDim.x)
        atomicAdd(&ap[idx], lp[idx] * w[idx / C2]);
}

__global__ void finalize_kernel(const float* __restrict__ b_out,
                                float* __restrict__ out) {
    int i = blockIdx.x * blockDim.x + threadIdx.x;
    if (i >= NN * C2) return;
    int nidx = i / C2;
    int c    = i - nidx * C2;
    const float* ap = g_accum + (size_t)nidx * D2 + c;
    float s = 0.f;
    #pragma unroll
    for (int h = 0; h < H2; h++) s += ap[h * C2];
    out[i] = s * (1.f / H2) + b_out[c];
}

// ---------------- launch ----------------
extern "C" void kernel_launch(void* const* d_in, const int* in_sizes, int n_in,
                              void* d_out, int out_size)
{
    const float* x     = (const float*)d_in[0];
    const void*  ei    = d_in[1];
    const float* Wq    = (const float*)d_in[2];
    const float* bq    = (const float*)d_in[3];
    const float* Wk    = (const float*)d_in[4];
    const float* bk    = (const float*)d_in[5];
    const float* Wv    = (const float*)d_in[6];
    const float* bv    = (const float*)d_in[7];
    const float* Wsk   = (const float*)d_in[8];
    const float* bsk   = (const float*)d_in[9];
    const float* Wl    = (const float*)d_in[10];
    const float* bl    = (const float*)d_in[11];
    const float* Wr    = (const float*)d_in[12];
    const float* br    = (const float*)d_in[13];
    const float* att   = (const float*)d_in[14];
    const float* b_out = (const float*)d_in[15];
    float* out = (float*)d_out;

    void *pq, *pk, *pv, *pskip, *pagg, *pgl, *pgr, *pamax1, *pden1, *pamax2, *pden2, *paccum;
    cudaGetSymbolAddress(&pq,     g_q);
    cudaGetSymbolAddress(&pk,     g_k);
    cudaGetSymbolAddress(&pv,     g_v);
    cudaGetSymbolAddress(&pskip,  g_skip);
    cudaGetSymbolAddress(&pagg,   g_agg);
    cudaGetSymbolAddress(&pgl,    g_gl);
    cudaGetSymbolAddress(&pgr,    g_gr);
    cudaGetSymbolAddress(&pamax1, g_amax1);
    cudaGetSymbolAddress(&pden1,  g_den1);
    cudaGetSymbolAddress(&pamax2, g_amax2);
    cudaGetSymbolAddress(&pden2,  g_den2);
    cudaGetSymbolAddress(&paccum, g_accum);

    // zero / init accumulators (needed every replay)
    cudaMemsetAsync(pagg,   0, (size_t)NN * D1 * sizeof(float));
    cudaMemsetAsync(pden1,  0, (size_t)NN * H1 * sizeof(float));
    cudaMemsetAsync(pden2,  0, (size_t)NN * H2 * sizeof(float));
    cudaMemsetAsync(paccum, 0, (size_t)NN * D2 * sizeof(float));
    fill_neginf<<<(NN * H1 + 255) / 256, 256>>>((float*)pamax1, NN * H1);
    fill_neginf<<<(NN * H2 + 255) / 256, 256>>>((float*)pamax2, NN * H2);

    // edge index
    detect_kernel<<<1, 1>>>((const int*)ei);
    convert_kernel<<<(EE + 255) / 256, 256>>>(ei);

    // layer-1 projections
    dim3 g1((D1 + TN - 1) / TN, (NN + TM - 1) / TM);
    sgemm_bias<<<g1, 256>>>(x, Wq,  bq,  (float*)pq,    NN, D1, INDIM);
    sgemm_bias<<<g1, 256>>>(x, Wk,  bk,  (float*)pk,    NN, D1, INDIM);
    sgemm_bias<<<g1, 256>>>(x, Wv,  bv,  (float*)pv,    NN, D1, INDIM);
    sgemm_bias<<<g1, 256>>>(x, Wsk, bsk, (float*)pskip, NN, D1, INDIM);

    // layer-1 attention
    alpha1_kernel<<<(EE * H1 * 32 + 255) / 256, 256>>>();
    exp1_kernel<<<(EE * H1 + 255) / 256, 256>>>();
    agg1_kernel<<<EE, 256>>>();
    elu_kernel<<<(NN * D1 + 255) / 256, 256>>>();

    // layer-2 projections (input = g_agg)
    dim3 g2((D2 + TN - 1) / TN, (NN + TM - 1) / TM);
    sgemm_bias<<<g2, 256>>>((const float*)pagg, Wl, bl, (float*)pgl, NN, D2, D1);
    sgemm_bias<<<g2, 256>>>((const float*)pagg, Wr, br, (float*)pgr, NN, D2, D1);

    // layer-2 attention
    alpha2_kernel<<<(E2 * H2 * 32 + 255) / 256, 256>>>(att);
    exp2_kernel<<<(E2 * H2 + 255) / 256, 256>>>();
    scatter2_kernel<<<E2, 256>>>();
    finalize_kernel<<<(NN * C2 + 255) / 256, 256>>>(b_out, out);
}

// round 3
// speedup vs baseline: 2.5198x; 2.5198x over previous
#include <cuda_runtime.h>
#include <cuda_bf16.h>
#include <math.h>
#include <stdint.h>

// ---------------- problem constants ----------------
#define NN      10000
#define EE      30000
#define INDIM   1024
#define H1      4
#define C1      512
#define D1      2048        // H1*C1
#define H2      8
#define C2      460
#define D2      3680        // H2*C2
#define E2      40000       // EE + NN (self loops appended)

// ---------------- GEMM tiling ----------------
#define BM 128
#define BN 128
#define BK 32
#define ASTR 36             // A smem row stride (floats): 32 + 4 pad
#define BSTR 136            // B smem row stride (floats): 128 + 8 pad
#define AS_BYTES (BM * ASTR * 4)        // 18432
#define BS_BYTES (BK * BSTR * 4)        // 17408
#define STAGE_BYTES (AS_BYTES + BS_BYTES)
#define SMEM_TOTAL (3 * STAGE_BYTES)    // 107520

// ---------------- device scratch (static, no allocs) ----------------
__device__ int   g_src[EE];
__device__ int   g_dst[EE];
__device__ int   g_is64;

__device__ float g_q   [(size_t)NN * D1];
__device__ float g_k   [(size_t)NN * D1];
__device__ float g_v   [(size_t)NN * D1];
__device__ float g_skip[(size_t)NN * D1];
__device__ float g_agg [(size_t)NN * D1];   // becomes h after elu

__device__ float g_alpha[EE * H1];
__device__ float g_amax1[NN * H1];
__device__ float g_den1 [NN * H1];

__device__ float g_gl  [(size_t)NN * D2];
__device__ float g_gr  [(size_t)NN * D2];

__device__ float g_a2   [E2 * H2];
__device__ float g_amax2[NN * H2];
__device__ float g_den2 [NN * H2];

__device__ float g_accum[(size_t)NN * D2];

// ---------------- helpers ----------------
__device__ __forceinline__ void atomicMaxFloat(float* addr, float val) {
    int* ai = (int*)addr;
    int old = *ai;
    while (__int_as_float(old) < val) {
        int assumed = old;
        old = atomicCAS(ai, assumed, __float_as_int(val));
        if (old == assumed) break;
    }
}

__device__ __forceinline__ uint32_t f2tf(float f) {
    uint32_t u;
    asm("cvt.rna.tf32.f32 %0, %1;" : "=r"(u) : "f"(f));
    return u;
}

__device__ __forceinline__ void mma_tf32(float* c, const uint32_t* a, const uint32_t* b) {
    asm volatile(
        "mma.sync.aligned.m16n8k8.row.col.f32.tf32.tf32.f32 "
        "{%0,%1,%2,%3}, {%4,%5,%6,%7}, {%8,%9}, {%0,%1,%2,%3};"
        : "+f"(c[0]), "+f"(c[1]), "+f"(c[2]), "+f"(c[3])
        : "r"(a[0]), "r"(a[1]), "r"(a[2]), "r"(a[3]), "r"(b[0]), "r"(b[1]));
}

// ---------------- edge_index dtype detect + convert ----------------
__global__ void detect_kernel(const int* w) {
    int all0 = 1;
    for (int i = 1; i < 4001; i += 2) {
        if (w[i] != 0) { all0 = 0; break; }
    }
    g_is64 = all0;
}

__global__ void convert_kernel(const void* ei) {
    int e = blockIdx.x * blockDim.x + threadIdx.x;
    if (e >= EE) return;
    if (g_is64) {
        const long long* p = (const long long*)ei;
        g_src[e] = (int)p[2 * e];
        g_dst[e] = (int)p[2 * e + 1];
    } else {
        const int* p = (const int*)ei;
        g_src[e] = p[2 * e];
        g_dst[e] = p[2 * e + 1];
    }
}

__global__ void fill_neginf(float* p, int n) {
    int i = blockIdx.x * blockDim.x + threadIdx.x;
    if (i < n) p[i] = -INFINITY;
}

// ---------------- tf32 mma.sync GEMM: C[M,N] = A[M,K] @ B[K,N] + bias ----------------
// 256 threads, 8 warps in 4(M) x 2(N); each warp computes 32x64.
// 3-stage cp.async pipeline.
__device__ __forceinline__ void gemm_load_stage(
    char* smem, int stage, const float* __restrict__ A, const float* __restrict__ B,
    int bm, int bn, int k0, int M, int N, int K)
{
    float* As = (float*)(smem + stage * STAGE_BYTES);
    float* Bs = (float*)(smem + stage * STAGE_BYTES + AS_BYTES);
    const int tid = threadIdx.x;
    // A tile: 128 rows x 32 cols, [m][k] layout, 1024 x 16B chunks, 4/thread
    #pragma unroll
    for (int t = 0; t < 4; t++) {
        int c   = tid + t * 256;
        int row = c >> 3;
        int kc  = (c & 7) << 2;
        int gr  = bm + row;
        int ok  = gr < M;
        const float* src = A + (size_t)(ok ? gr : 0) * K + k0 + kc;
        uint32_t dst;
        asm("{ .reg .u64 tt; cvta.to.shared.u64 tt, %1; cvt.u32.u64 %0, tt; }"
            : "=r"(dst) : "l"(As + row * ASTR + kc));
        asm volatile("cp.async.cg.shared.global [%0], [%1], 16, %2;"
                     :: "r"(dst), "l"(src), "r"(ok ? 16 : 0) : "memory");
    }
    // B tile: 32 rows x 128 cols, [k][n] layout, 1024 x 16B chunks, 4/thread
    #pragma unroll
    for (int t = 0; t < 4; t++) {
        int c    = tid + t * 256;
        int krow = c >> 5;
        int nc   = (c & 31) << 2;
        int gc   = bn + nc;
        int ok   = gc < N;                  // N % 4 == 0 so chunk-uniform
        const float* src = B + (size_t)(k0 + krow) * N + (ok ? gc : 0);
        uint32_t dst;
        asm("{ .reg .u64 tt; cvta.to.shared.u64 tt, %1; cvt.u32.u64 %0, tt; }"
            : "=r"(dst) : "l"(Bs + krow * BSTR + nc));
        asm volatile("cp.async.cg.shared.global [%0], [%1], 16, %2;"
                     :: "r"(dst), "l"(src), "r"(ok ? 16 : 0) : "memory");
    }
}

__global__ __launch_bounds__(256)
void gemm_tc(const float* __restrict__ A, const float* __restrict__ B,
             const float* __restrict__ bias, float* __restrict__ C,
             int M, int N, int K)
{
    extern __shared__ char smem[];
    const int tid  = threadIdx.x;
    const int wid  = tid >> 5;
    const int lane = tid & 31;
    const int tg   = lane >> 2;     // group id 0..7
    const int tig  = lane & 3;      // thread-in-group 0..3
    const int wm   = wid & 3;       // 0..3 -> M offset wm*32
    const int wn   = wid >> 2;      // 0..1 -> N offset wn*64
    const int bm   = blockIdx.y * BM;
    const int bn   = blockIdx.x * BN;
    const int nk   = K / BK;

    float acc[2][8][4];
    #pragma unroll
    for (int mi = 0; mi < 2; mi++)
        #pragma unroll
        for (int ni = 0; ni < 8; ni++)
            #pragma unroll
            for (int r = 0; r < 4; r++) acc[mi][ni][r] = 0.f;

    // prologue: stages 0, 1
    gemm_load_stage(smem, 0, A, B, bm, bn, 0, M, N, K);
    asm volatile("cp.async.commit_group;" ::: "memory");
    gemm_load_stage(smem, 1, A, B, bm, bn, BK, M, N, K);
    asm volatile("cp.async.commit_group;" ::: "memory");

    for (int kt = 0; kt < nk; kt++) {
        asm volatile("cp.async.wait_group 1;" ::: "memory");
        __syncthreads();

        const int buf = kt - (kt / 3) * 3;
        const float* As = (const float*)(smem + buf * STAGE_BYTES);
        const float* Bs = (const float*)(smem + buf * STAGE_BYTES + AS_BYTES);

        #pragma unroll
        for (int ks = 0; ks < 4; ks++) {
            const int kk = ks * 8;
            uint32_t af[2][4];
            #pragma unroll
            for (int mi = 0; mi < 2; mi++) {
                const float* ap = As + (wm * 32 + mi * 16 + tg) * ASTR + kk + tig;
                af[mi][0] = f2tf(ap[0]);
                af[mi][2] = f2tf(ap[4]);
                af[mi][1] = f2tf(ap[8 * ASTR]);
                af[mi][3] = f2tf(ap[8 * ASTR + 4]);
            }
            uint32_t bf[8][2];
            #pragma unroll
            for (int ni = 0; ni < 8; ni++) {
                const float* bp = Bs + (kk + tig) * BSTR + wn * 64 + ni * 8 + tg;
                bf[ni][0] = f2tf(bp[0]);
                bf[ni][1] = f2tf(bp[4 * BSTR]);
            }
            #pragma unroll
            for (int mi = 0; mi < 2; mi++)
                #pragma unroll
                for (int ni = 0; ni < 8; ni++)
                    mma_tf32(acc[mi][ni], af[mi], bf[ni]);
        }

        __syncthreads();
        if (kt + 2 < nk) {
            const int nb = (kt + 2) - ((kt + 2) / 3) * 3;
            gemm_load_stage(smem, nb, A, B, bm, bn, (kt + 2) * BK, M, N, K);
        }
        asm volatile("cp.async.commit_group;" ::: "memory");
    }

    // epilogue
    #pragma unroll
    for (int mi = 0; mi < 2; mi++) {
        int r0 = bm + wm * 32 + mi * 16 + tg;
        #pragma unroll
        for (int ni = 0; ni < 8; ni++) {
            int col = bn + wn * 64 + ni * 8 + 2 * tig;
            if (col >= N) continue;
            float b0 = bias[col], b1 = bias[col + 1];
            if (r0 < M) {
                float2 o = make_float2(acc[mi][ni][0] + b0, acc[mi][ni][1] + b1);
                *(float2*)(C + (size_t)r0 * N + col) = o;
            }
            if (r0 + 8 < M) {
                float2 o = make_float2(acc[mi][ni][2] + b0, acc[mi][ni][3] + b1);
                *(float2*)(C + (size_t)(r0 + 8) * N + col) = o;
            }
        }
    }
}

// ---------------- layer 1 attention ----------------
__global__ void alpha1_kernel() {
    int gw   = (blockIdx.x * blockDim.x + threadIdx.x) >> 5;
    int lane = threadIdx.x & 31;
    if (gw >= EE * H1) return;
    int e = gw >> 2, h = gw & 3;
    int s = g_src[e], d = g_dst[e];
    const float4* qp = (const float4*)(g_q + (size_t)d * D1 + h * C1);
    const float4* kp = (const float4*)(g_k + (size_t)s * D1 + h * C1);
    float sum = 0.f;
    #pragma unroll
    for (int c = lane; c < C1 / 4; c += 32) {
        float4 a = qp[c], b = kp[c];
        sum += a.x * b.x + a.y * b.y + a.z * b.z + a.w * b.w;
    }
    #pragma unroll
    for (int o = 16; o; o >>= 1) sum += __shfl_xor_sync(0xFFFFFFFFu, sum, o);
    if (lane == 0) {
        float val = sum * 0.04419417382415922f;  // 1/sqrt(512)
        g_alpha[e * H1 + h] = val;
        atomicMaxFloat(&g_amax1[d * H1 + h], val);
    }
}

__global__ void exp1_kernel() {
    int i = blockIdx.x * blockDim.x + threadIdx.x;
    if (i >= EE * H1) return;
    int e = i >> 2, h = i & 3;
    int d = g_dst[e];
    float ex = expf(g_alpha[i] - g_amax1[d * H1 + h]);
    g_alpha[i] = ex;
    atomicAdd(&g_den1[d * H1 + h], ex);
}

__global__ void agg1_kernel() {
    __shared__ float w[H1];
    int e = blockIdx.x;
    int s = g_src[e], d = g_dst[e];
    if (threadIdx.x < H1)
        w[threadIdx.x] = g_alpha[e * H1 + threadIdx.x] /
                         (g_den1[d * H1 + threadIdx.x] + 1e-16f);
    __syncthreads();
    const float* vp = g_v   + (size_t)s * D1;
    float*       ap = g_agg + (size_t)d * D1;
    for (int idx = threadIdx.x; idx < D1; idx += blockDim.x)
        atomicAdd(&ap[idx], vp[idx] * w[idx >> 9]);
}

__global__ void elu_kernel() {
    int i = blockIdx.x * blockDim.x + threadIdx.x;
    if (i >= NN * D1) return;
    float x = g_agg[i] + g_skip[i];
    g_agg[i] = x > 0.f ? x : expm1f(x);
}

// ---------------- layer 2 attention ----------------
__global__ void alpha2_kernel(const float* __restrict__ att) {
    int gw   = (blockIdx.x * blockDim.x + threadIdx.x) >> 5;
    int lane = threadIdx.x & 31;
    if (gw >= E2 * H2) return;
    int ee = gw >> 3, h = gw & 7;
    int s = ee < EE ? g_src[ee] : ee - EE;
    int d = ee < EE ? g_dst[ee] : ee - EE;
    const float* lp = g_gl + (size_t)s * D2 + h * C2;
    const float* rp = g_gr + (size_t)d * D2 + h * C2;
    const float* ap = att + h * C2;
    float sum = 0.f;
    for (int c = lane; c < C2; c += 32) {
        float eo = lp[c] + rp[c];
        eo = eo > 0.f ? eo : 0.2f * eo;
        sum += eo * ap[c];
    }
    #pragma unroll
    for (int o = 16; o; o >>= 1) sum += __shfl_xor_sync(0xFFFFFFFFu, sum, o);
    if (lane == 0) {
        g_a2[ee * H2 + h] = sum;
        atomicMaxFloat(&g_amax2[d * H2 + h], sum);
    }
}

__global__ void exp2_kernel() {
    int i = blockIdx.x * blockDim.x + threadIdx.x;
    if (i >= E2 * H2) return;
    int ee = i >> 3, h = i & 7;
    int d = ee < EE ? g_dst[ee] : ee - EE;
    float ex = expf(g_a2[i] - g_amax2[d * H2 + h]);
    g_a2[i] = ex;
    atomicAdd(&g_den2[d * H2 + h], ex);
}

__global__ void scatter2_kernel() {
    __shared__ float w[H2];
    int ee = blockIdx.x;
    int s = ee < EE ? g_src[ee] : ee - EE;
    int d = ee < EE ? g_dst[ee] : ee - EE;
    if (threadIdx.x < H2)
        w[threadIdx.x] = g_a2[ee * H2 + threadIdx.x] /
                         (g_den2[d * H2 + threadIdx.x] + 1e-16f);
    __syncthreads();
    const float* lp = g_gl    + (size_t)s * D2;
    float*       ap = g_accum + (size_t)d * D2;
    for (int idx = threadIdx.x; idx < D2; idx += blockDim.x)
        atomicAdd(&ap[idx], lp[idx] * w[idx / C2]);
}

__global__ void finalize_kernel(const float* __restrict__ b_out,
                                float* __restrict__ out) {
    int i = blockIdx.x * blockDim.x + threadIdx.x;
    if (i >= NN * C2) return;
    int nidx = i / C2;
    int c    = i - nidx * C2;
    const float* ap = g_accum + (size_t)nidx * D2 + c;
    float s = 0.f;
    #pragma unroll
    for (int h = 0; h < H2; h++) s += ap[h * C2];
    out[i] = s * (1.f / H2) + b_out[c];
}

// ---------------- launch ----------------
extern "C" void kernel_launch(void* const* d_in, const int* in_sizes, int n_in,
                              void* d_out, int out_size)
{
    const float* x     = (const float*)d_in[0];
    const void*  ei    = d_in[1];
    const float* Wq    = (const float*)d_in[2];
    const float* bq    = (const float*)d_in[3];
    const float* Wk    = (const float*)d_in[4];
    const float* bk    = (const float*)d_in[5];
    const float* Wv    = (const float*)d_in[6];
    const float* bv    = (const float*)d_in[7];
    const float* Wsk   = (const float*)d_in[8];
    const float* bsk   = (const float*)d_in[9];
    const float* Wl    = (const float*)d_in[10];
    const float* bl    = (const float*)d_in[11];
    const float* Wr    = (const float*)d_in[12];
    const float* br    = (const float*)d_in[13];
    const float* att   = (const float*)d_in[14];
    const float* b_out = (const float*)d_in[15];
    float* out = (float*)d_out;

    void *pq, *pk, *pv, *pskip, *pagg, *pgl, *pgr, *pamax1, *pden1, *pamax2, *pden2, *paccum;
    cudaGetSymbolAddress(&pq,     g_q);
    cudaGetSymbolAddress(&pk,     g_k);
    cudaGetSymbolAddress(&pv,     g_v);
    cudaGetSymbolAddress(&pskip,  g_skip);
    cudaGetSymbolAddress(&pagg,   g_agg);
    cudaGetSymbolAddress(&pgl,    g_gl);
    cudaGetSymbolAddress(&pgr,    g_gr);
    cudaGetSymbolAddress(&pamax1, g_amax1);
    cudaGetSymbolAddress(&pden1,  g_den1);
    cudaGetSymbolAddress(&pamax2, g_amax2);
    cudaGetSymbolAddress(&pden2,  g_den2);
    cudaGetSymbolAddress(&paccum, g_accum);

    cudaFuncSetAttribute(gemm_tc, cudaFuncAttributeMaxDynamicSharedMemorySize, SMEM_TOTAL);

    // zero / init accumulators (needed every replay)
    cudaMemsetAsync(pagg,   0, (size_t)NN * D1 * sizeof(float));
    cudaMemsetAsync(pden1,  0, (size_t)NN * H1 * sizeof(float));
    cudaMemsetAsync(pden2,  0, (size_t)NN * H2 * sizeof(float));
    cudaMemsetAsync(paccum, 0, (size_t)NN * D2 * sizeof(float));
    fill_neginf<<<(NN * H1 + 255) / 256, 256>>>((float*)pamax1, NN * H1);
    fill_neginf<<<(NN * H2 + 255) / 256, 256>>>((float*)pamax2, NN * H2);

    // edge index
    detect_kernel<<<1, 1>>>((const int*)ei);
    convert_kernel<<<(EE + 255) / 256, 256>>>(ei);

    // layer-1 projections: [10000,1024] @ [1024,2048]
    dim3 g1((D1 + BN - 1) / BN, (NN + BM - 1) / BM);
    gemm_tc<<<g1, 256, SMEM_TOTAL>>>(x, Wq,  bq,  (float*)pq,    NN, D1, INDIM);
    gemm_tc<<<g1, 256, SMEM_TOTAL>>>(x, Wk,  bk,  (float*)pk,    NN, D1, INDIM);
    gemm_tc<<<g1, 256, SMEM_TOTAL>>>(x, Wv,  bv,  (float*)pv,    NN, D1, INDIM);
    gemm_tc<<<g1, 256, SMEM_TOTAL>>>(x, Wsk, bsk, (float*)pskip, NN, D1, INDIM);

    // layer-1 attention
    alpha1_kernel<<<(EE * H1 * 32 + 255) / 256, 256>>>();
    exp1_kernel<<<(EE * H1 + 255) / 256, 256>>>();
    agg1_kernel<<<EE, 256>>>();
    elu_kernel<<<(NN * D1 + 255) / 256, 256>>>();

    // layer-2 projections: [10000,2048] @ [2048,3680]
    dim3 g2((D2 + BN - 1) / BN, (NN + BM - 1) / BM);
    gemm_tc<<<g2, 256, SMEM_TOTAL>>>((const float*)pagg, Wl, bl, (float*)pgl, NN, D2, D1);
    gemm_tc<<<g2, 256, SMEM_TOTAL>>>((const float*)pagg, Wr, br, (float*)pgr, NN, D2, D1);

    // layer-2 attention
    alpha2_kernel<<<(E2 * H2 * 32 + 255) / 256, 256>>>(att);
    exp2_kernel<<<(E2 * H2 + 255) / 256, 256>>>();
    scatter2_kernel<<<E2, 256>>>();
    finalize_kernel<<<(NN * C2 + 255) / 256, 256>>>(b_out, out);
}